// round 1
// baseline (speedup 1.0000x reference)
#include <cuda_runtime.h>
#include <math.h>

// ---------------------------------------------------------------------------
// SelectiveModel: B=32768, T=23 steps, H=64, SLOTS=8, VOCAB=64.
//
// Structural collapse:
//  - mem slots only ever contain embed[tok] for tok in 0..63 (all 8 slots are
//    filled during t=0..7). So the gating MLP score depends only on
//    (ctx_token, mem_token): precompute S[64][64] = sigmoid(score).
//  - recurrence becomes integer-state: 8 token ids + table argmax per step.
//  - readout layer 1 splits: pre1 = QP[query_tok] + (1/8) * sum_s MP[mem_tok_s]
//    with QP[v] = embed[v] @ rw1[0:64] + rb1, MP[v] = embed[v] @ rw1[64:128].
//  - only the 64x64 layer-2 GEMV (4096 MACs/batch) remains as FP work.
// ---------------------------------------------------------------------------

__device__ float g_S [64 * 64];   // sigmoid score table
__device__ float g_QP[66 * 68];   // query part of layer-1 (+rb1), padded rows
__device__ float g_MP[64 * 68];   // memory part of layer-1, padded rows

// ============================ K1: table precompute ==========================
// grid = 129 blocks x 128 threads
//   blocks   0..63 : one S-table row (ctx token c = blockIdx.x)
//   blocks  64..96 : QP rows (2 rows per block, 66 rows total)
//   blocks 97..128 : MP rows (2 rows per block, 64 rows total)
__global__ void __launch_bounds__(128) precompute_kernel(
    const float* __restrict__ embed, const float* __restrict__ gw1,
    const float* __restrict__ gb1,   const float* __restrict__ gw2,
    const float* __restrict__ gb2,   const float* __restrict__ rw1,
    const float* __restrict__ rb1)
{
    const int bid = blockIdx.x, tid = threadIdx.x;
    if (bid < 64) {
        // ---- S row for ctx token c = bid ----
        __shared__ float sEmb [64 * 65];   // padded (bank spread)
        __shared__ float sGw1 [128 * 32];
        __shared__ float sEdot[32];
        __shared__ float sMdot[64 * 33];   // padded
        for (int i = tid; i < 64 * 64; i += 128)
            sEmb[(i >> 6) * 65 + (i & 63)] = embed[i];
        for (int i = tid; i < 128 * 32; i += 128) sGw1[i] = gw1[i];
        __syncthreads();
        const int c = bid;
        if (tid < 32) {                    // edot[j] = e_c @ gw1[0:64, j]
            float acc = 0.f;
            #pragma unroll 16
            for (int k = 0; k < 64; k++) acc += sEmb[c * 65 + k] * sGw1[k * 32 + tid];
            sEdot[tid] = acc;
        }
        {                                  // mdot[m][j] = e_m @ gw1[64:128, j]
            const int m = tid & 63, half = tid >> 6;
            float acc[16];
            #pragma unroll
            for (int jj = 0; jj < 16; jj++) acc[jj] = 0.f;
            for (int k = 0; k < 64; k++) {
                const float e = sEmb[m * 65 + k];
                #pragma unroll
                for (int jj = 0; jj < 16; jj++)
                    acc[jj] += e * sGw1[(64 + k) * 32 + half * 16 + jj];
            }
            #pragma unroll
            for (int jj = 0; jj < 16; jj++) sMdot[m * 33 + half * 16 + jj] = acc[jj];
        }
        __syncthreads();
        if (tid < 64) {                    // score -> sigmoid
            float acc = gb2[0];
            #pragma unroll
            for (int j = 0; j < 32; j++) {
                const float hv = sEdot[j] + sMdot[tid * 33 + j] + gb1[j];
                acc += fmaxf(hv, 0.f) * gw2[j];
            }
            g_S[c * 64 + tid] = 1.f / (1.f + expf(-acc));
        }
    } else if (bid < 97) {
        // ---- QP rows (include rb1) ----
        const int r = (bid - 64) * 2 + (tid >> 6);
        const int j = tid & 63;
        if (r < 66) {
            float acc = rb1[j];
            #pragma unroll 16
            for (int k = 0; k < 64; k++) acc += embed[r * 64 + k] * rw1[k * 64 + j];
            g_QP[r * 68 + j] = acc;
            if (j < 4) g_QP[r * 68 + 64 + j] = 0.f;   // zero pad
        }
    } else {
        // ---- MP rows ----
        const int r = (bid - 97) * 2 + (tid >> 6);
        const int j = tid & 63;
        float acc = 0.f;
        #pragma unroll 16
        for (int k = 0; k < 64; k++) acc += embed[r * 64 + k] * rw1[(64 + k) * 64 + j];
        g_MP[r * 68 + j] = acc;
        if (j < 4) g_MP[r * 68 + 64 + j] = 0.f;       // zero pad
    }
}

// ============================== K2: main ====================================
// grid = 256 blocks x 128 threads; thread = one batch row.
// Dynamic smem layout (floats):
//   sS[4096] | sQP[66*68=4488] | sMP[64*68=4352] | sRW2[4096] |
//   sStage[4*32*9=1152] | tok bytes [128*24 = 768 floats]
#define K2_SMEM_FLOATS (4096 + 4488 + 4352 + 4096 + 1152 + 768)
#define K2_SMEM_BYTES  (K2_SMEM_FLOATS * 4)

__global__ void __launch_bounds__(128) main_kernel(
    const int* __restrict__ seqs32, const int* __restrict__ qtok32,
    const float* __restrict__ rw2,  const float* __restrict__ rb2,
    float* __restrict__ out)
{
    extern __shared__ float smem[];
    float* sS     = smem;
    float* sQP    = smem + 4096;
    float* sMP    = sQP + 4488;
    float* sRW2   = sMP + 4352;
    float* sStage = sRW2 + 4096;
    unsigned char* sTok = (unsigned char*)(sStage + 1152);
    const int tid = threadIdx.x, bid = blockIdx.x;

    // Detect int64 vs int32 token arrays (int64 LE of small values -> odd
    // 32-bit words are all zero; P(false positive with int32 tokens) ~ 64^-8).
    const int oddOr = seqs32[1] | seqs32[3] | seqs32[5] | seqs32[7] |
                      seqs32[9] | seqs32[11] | seqs32[13] | seqs32[15];
    const bool is64 = (oddOr == 0);

    // ---- tables -> shared (linear float4 copies) ----
    {
        const float4* g; float4* s;
        g = (const float4*)g_S;   s = (float4*)sS;   for (int i = tid; i < 1024; i += 128) s[i] = g[i];
        g = (const float4*)g_QP;  s = (float4*)sQP;  for (int i = tid; i < 1122; i += 128) s[i] = g[i];
        g = (const float4*)g_MP;  s = (float4*)sMP;  for (int i = tid; i < 1088; i += 128) s[i] = g[i];
        g = (const float4*)rw2;   s = (float4*)sRW2; for (int i = tid; i < 1024; i += 128) s[i] = g[i];
    }
    // ---- stage this block's 128 seq rows as token bytes (coalesced) ----
    {
        const int base = bid * 128 * 24;
        for (int i = tid; i < 128 * 24; i += 128) {
            const int v = is64 ? seqs32[2 * (base + i)] : seqs32[base + i];
            sTok[i] = (unsigned char)v;
        }
    }
    const int b  = bid * 128 + tid;
    const int qt = is64 ? qtok32[2 * b] : qtok32[b];
    __syncthreads();

    // ---- recurrence: integer slot state + table argmax ----
    const unsigned char* myTok = sTok + tid * 24;
    int mt[8];
    #pragma unroll
    for (int s = 0; s < 8; s++) mt[s] = myTok[s];      // t = 0..7 fill slots
    #pragma unroll
    for (int t = 8; t < 23; t++) {
        const int c = myTok[t];
        const float* Srow = sS + (c << 6);
        float best = Srow[mt[0]];
        int bi = 0;
        #pragma unroll
        for (int s = 1; s < 8; s++) {
            const float sc = Srow[mt[s]];
            if (sc > best) { best = sc; bi = s; }      // strict > == first-max
        }
        #pragma unroll
        for (int s = 0; s < 8; s++) if (bi == s) mt[s] = c;
    }

    // ---- layer 1 via tables: h = relu(QP[qt] + 0.125 * sum_s MP[mt[s]]) ----
    float h[64];
    {
        const float4* qp = (const float4*)(sQP + qt * 68);   // 272B rows: f4 ok
        #pragma unroll
        for (int i = 0; i < 16; i++) {
            const float4 a = qp[i];
            h[4*i+0] = a.x; h[4*i+1] = a.y; h[4*i+2] = a.z; h[4*i+3] = a.w;
        }
        #pragma unroll
        for (int s = 0; s < 8; s++) {
            const float4* mp = (const float4*)(sMP + mt[s] * 68);
            #pragma unroll
            for (int i = 0; i < 16; i++) {
                const float4 a = mp[i];
                h[4*i+0] += 0.125f * a.x; h[4*i+1] += 0.125f * a.y;
                h[4*i+2] += 0.125f * a.z; h[4*i+3] += 0.125f * a.w;
            }
        }
        #pragma unroll
        for (int j = 0; j < 64; j++) h[j] = fmaxf(h[j], 0.f);
    }

    // ---- layer 2 (64x64 GEMV) + warp-staged coalesced store ----
    const int lane = tid & 31, w = tid >> 5;
    float* st = sStage + w * 288;                       // [32][9] per warp
    const int b0 = bid * 128 + w * 32;
    #pragma unroll 1
    for (int vc = 0; vc < 64; vc += 8) {
        float acc[8];
        #pragma unroll
        for (int v = 0; v < 8; v++) acc[v] = rb2[vc + v];   // uniform L1 load
        #pragma unroll
        for (int j = 0; j < 64; j++) {
            const float4* wp = (const float4*)(sRW2 + (j << 6) + vc);
            const float4 w0 = wp[0], w1 = wp[1];            // uniform-addr LDS
            const float hj = h[j];
            acc[0] += hj * w0.x; acc[1] += hj * w0.y;
            acc[2] += hj * w0.z; acc[3] += hj * w0.w;
            acc[4] += hj * w1.x; acc[5] += hj * w1.y;
            acc[6] += hj * w1.z; acc[7] += hj * w1.w;
        }
        #pragma unroll
        for (int v = 0; v < 8; v++) st[lane * 9 + v] = acc[v];  // stride-9: no conflicts
        __syncwarp();
        #pragma unroll
        for (int i = 0; i < 8; i++) {
            const int row = (lane >> 3) + i * 4;
            out[(b0 + row) * 64 + vc + (lane & 7)] = st[row * 9 + (lane & 7)];
        }
        __syncwarp();
    }
}

// ============================== launch ======================================
extern "C" void kernel_launch(void* const* d_in, const int* in_sizes, int n_in,
                              void* d_out, int out_size)
{
    const int*   seqs  = (const int*)  d_in[0];
    const int*   qtok  = (const int*)  d_in[1];
    const float* embed = (const float*)d_in[2];
    const float* gw1   = (const float*)d_in[3];
    const float* gb1   = (const float*)d_in[4];
    const float* gw2   = (const float*)d_in[5];
    const float* gb2   = (const float*)d_in[6];
    const float* rw1   = (const float*)d_in[7];
    const float* rb1   = (const float*)d_in[8];
    const float* rw2   = (const float*)d_in[9];
    const float* rb2   = (const float*)d_in[10];

    cudaFuncSetAttribute(main_kernel,
                         cudaFuncAttributeMaxDynamicSharedMemorySize,
                         K2_SMEM_BYTES);

    precompute_kernel<<<129, 128>>>(embed, gw1, gb1, gw2, gb2, rw1, rb1);
    main_kernel<<<256, 128, K2_SMEM_BYTES>>>(seqs, qtok, rw2, rb2, (float*)d_out);
}